// round 14
// baseline (speedup 1.0000x reference)
#include <cuda_runtime.h>
#include <stdint.h>
#include <math.h>

// Shapes: F: (2,3,128,128,128) = 12,582,912 ; I/S: (2,1,128,128,128) = 4,194,304
#define DIM   128
#define DIM2  (128*128)
#define VOL   (128*128*128)
#define NF    12582912
#define NI    4194304

#define NT    384          // 12 warps

// LCC: 2 x-tiles(64) * 16 z-chunks(8) * 2 y-halves(64) * 2 batch * 2 pair = 256
#define NLCC  256
#define NFRED 320
#define NSRED 96
#define NBLK  768          // role = bid % 3 ; r3==1 -> LCC

__device__ double g_acc[12];
__device__ unsigned int g_count;

__device__ __forceinline__ void pf_l2(const float* p) {
    asm volatile("prefetch.global.L2 [%0];" :: "l"(p));
}

__device__ __forceinline__ double bred(double v, double* sh) {
    #pragma unroll
    for (int o = 16; o > 0; o >>= 1) v += __shfl_down_sync(0xffffffffu, v, o);
    int lane = threadIdx.x & 31, wid = threadIdx.x >> 5;
    if (lane == 0) sh[wid] = v;
    __syncthreads();
    if (wid == 0) {
        v = (lane < (NT >> 5)) ? sh[lane] : 0.0;
        #pragma unroll
        for (int o = 8; o > 0; o >>= 1) v += __shfl_down_sync(0xffffffffu, v, o);
    }
    return v;  // valid on thread 0
}

// 5-tap x-window sums for the 2 outputs this lane owns (x = 2*tx, 2*tx+1).
__device__ __forceinline__ float2 xsum5(float2 v, float2 h, int tx) {
    float lmx = __shfl_up_sync(0xffffffffu, v.x, 1);
    float lmy = __shfl_up_sync(0xffffffffu, v.y, 1);
    float rpx = __shfl_down_sync(0xffffffffu, v.x, 1);
    float rpy = __shfl_down_sync(0xffffffffu, v.y, 1);
    if (tx == 0)  { lmx = h.x; lmy = h.y; }
    if (tx == 31) { rpx = h.x; rpy = h.y; }
    float m = lmy + v.x + v.y + rpx;
    return make_float2(lmx + m, m + rpy);
}

__global__ __launch_bounds__(NT, 2) void main_kernel(
    const float* __restrict__ F0,  const float* __restrict__ F0g,
    const float* __restrict__ I0,  const float* __restrict__ I0R,
    const float* __restrict__ I1,  const float* __restrict__ I1R,
    const float* __restrict__ S0,  const float* __restrict__ S0g,
    const float* __restrict__ S1,  const float* __restrict__ S1g,
    float* __restrict__ out)
{
    __shared__ __align__(16) float ybuf[2][2][12][128];   // [buf][row][plane][G,P interleaved] = 24 KB
    __shared__ double sh[12];
    __shared__ unsigned int s_last;

    const int bid = blockIdx.x;
    const int tid = threadIdx.x;
    const int r3  = bid % 3;

    if (r3 == 1) {
        // ===== LCC: 2 rows per iteration / x-in-lanes / z-across-warps =====
        int sub = bid / 3;
        int xt = sub & 1;  sub >>= 1;
        int zc = sub & 15; sub >>= 4;
        int yh = sub & 1;  sub >>= 1;
        int b  = sub & 1;  sub >>= 1;
        int pair = sub;

        const float* __restrict__ G = pair ? I1  : I0;
        const float* __restrict__ P = pair ? I1R : I0R;

        const int x0 = xt * 64, z0 = zc * 8, y0 = yh * 64;
        const int tx = tid & 31, w = tid >> 5;      // warp w owns plane z0-2+w
        const int z  = z0 - 2 + w;
        const bool zok = (unsigned)z < DIM;

        const size_t pbase = (size_t)b * VOL + (size_t)(zok ? z : 0) * DIM2
                             + (size_t)x0 + 2 * tx;
        const float* __restrict__ gp = G + pbase;
        const float* __restrict__ pp = P + pbase;

        const bool isL = (tx == 0), isR = (tx == 31);
        const bool haloAct = (isL && x0 > 0) || (isR && x0 + 64 < DIM);
        const int  hoff = isL ? -2 : 2;             // halo offset for lanes 0/31
        const bool pfl  = zok && ((tx & 15) == 0);  // prefetch lanes (0,16): 2x128B per row

        const float2 zz = make_float2(0.f, 0.f);

        // current rows 2i, 2i+1 (start: rows 0,1 = y0-2, y0-1)
        float2 vG0 = zz, vG1 = zz, vP0 = zz, vP1 = zz;
        float2 hG0 = zz, hG1 = zz, hP0 = zz, hP1 = zz;
        if (zok) {
            int gy0 = y0 - 2, gy1 = y0 - 1;
            if ((unsigned)gy0 < DIM) {
                size_t ro = (size_t)gy0 * DIM;
                vG0 = *(const float2*)(gp + ro);
                vP0 = *(const float2*)(pp + ro);
                if (haloAct) { hG0 = *(const float2*)(gp + ro + hoff);
                               hP0 = *(const float2*)(pp + ro + hoff); }
            }
            if ((unsigned)gy1 < DIM) {
                size_t ro = (size_t)gy1 * DIM;
                vG1 = *(const float2*)(gp + ro);
                vP1 = *(const float2*)(pp + ro);
                if (haloAct) { hG1 = *(const float2*)(gp + ro + hoff);
                               hP1 = *(const float2*)(pp + ro + hoff); }
            }
        }

        float2 rG[6] = {zz, zz, zz, zz, zz, zz};    // x-sum ring (rows 2i-4 .. 2i+1)
        float2 rP[6] = {zz, zz, zz, zz, zz, zz};
        float2 cG0 = zz, cG1 = zz, cP0 = zz, cP1 = zz;   // centers (rows 2i-2, 2i-1)
        float agp = 0.f, agg = 0.f, app = 0.f;
        const bool mainw = (w >= 2) && (w <= 9);
        int bufsel = 0;

        for (int i = 0; i < 34; i++) {
            // L2 prefetch rows 2i+4, 2i+5 (2 iterations ahead; 2 lanes cover the warp row)
            if (pfl && i < 32) {
                int gyp = y0 + 2 + 2 * i;          // y of row 2i+4
                if ((unsigned)gyp < DIM) {
                    size_t ro = (size_t)gyp * DIM;
                    pf_l2(gp + ro); pf_l2(pp + ro);
                }
                int gyq = gyp + 1;
                if ((unsigned)gyq < DIM) {
                    size_t ro = (size_t)gyq * DIM;
                    pf_l2(gp + ro); pf_l2(pp + ro);
                }
            }

            // prefetch rows 2i+2, 2i+3 into registers
            float2 nG0 = zz, nG1 = zz, nP0 = zz, nP1 = zz;
            float2 nhG0 = zz, nhG1 = zz, nhP0 = zz, nhP1 = zz;
            if (i < 33 && zok) {
                int gy0 = y0 + 2 * i;          // y of row 2i+2
                int gy1 = gy0 + 1;
                if ((unsigned)gy0 < DIM) {
                    size_t ro = (size_t)gy0 * DIM;
                    nG0 = *(const float2*)(gp + ro);
                    nP0 = *(const float2*)(pp + ro);
                    if (haloAct) { nhG0 = *(const float2*)(gp + ro + hoff);
                                   nhP0 = *(const float2*)(pp + ro + hoff); }
                }
                if ((unsigned)gy1 < DIM) {
                    size_t ro = (size_t)gy1 * DIM;
                    nG1 = *(const float2*)(gp + ro);
                    nP1 = *(const float2*)(pp + ro);
                    if (haloAct) { nhG1 = *(const float2*)(gp + ro + hoff);
                                   nhP1 = *(const float2*)(pp + ro + hoff); }
                }
            }

            // x 5-tap for both rows
            float2 x0G = xsum5(vG0, hG0, tx);
            float2 x1G = xsum5(vG1, hG1, tx);
            float2 x0P = xsum5(vP0, hP0, tx);
            float2 x1P = xsum5(vP1, hP1, tx);

            // ring shift by 2, insert
            rG[0] = rG[2]; rG[1] = rG[3]; rG[2] = rG[4]; rG[3] = rG[5];
            rG[4] = x0G;   rG[5] = x1G;
            rP[0] = rP[2]; rP[1] = rP[3]; rP[2] = rP[4]; rP[3] = rP[5];
            rP[4] = x0P;   rP[5] = x1P;

            // y 5-tap: shared partial m = r1+r2+r3+r4
            float mGx = rG[1].x + rG[2].x + rG[3].x + rG[4].x;
            float mGy = rG[1].y + rG[2].y + rG[3].y + rG[4].y;
            float mPx = rP[1].x + rP[2].x + rP[3].x + rP[4].x;
            float mPy = rP[1].y + rP[2].y + rP[3].y + rP[4].y;
            float y0Gx = rG[0].x + mGx, y0Gy = rG[0].y + mGy;
            float y1Gx = mGx + rG[5].x, y1Gy = mGy + rG[5].y;
            float y0Px = rP[0].x + mPx, y0Py = rP[0].y + mPy;
            float y1Px = mPx + rP[5].x, y1Py = mPy + rP[5].y;

            // publish xy-sums: 2 dense STS.128
            *(float4*)&ybuf[bufsel][0][w][4 * tx] = make_float4(y0Gx, y0Px, y0Gy, y0Py);
            *(float4*)&ybuf[bufsel][1][w][4 * tx] = make_float4(y1Gx, y1Px, y1Gy, y1Py);
            __syncthreads();   // single barrier per 2 rows

            // z 5-tap + accumulate for output rows 2i-2, 2i-1
            if (mainw && i >= 2) {
                float z0gx = 0.f, z0gy = 0.f, z0px = 0.f, z0py = 0.f;
                float z1gx = 0.f, z1gy = 0.f, z1px = 0.f, z1py = 0.f;
                #pragma unroll
                for (int d = 0; d < 5; d++) {
                    float4 q0 = *(const float4*)&ybuf[bufsel][0][w - 2 + d][4 * tx];
                    float4 q1 = *(const float4*)&ybuf[bufsel][1][w - 2 + d][4 * tx];
                    z0gx += q0.x; z0px += q0.y; z0gy += q0.z; z0py += q0.w;
                    z1gx += q1.x; z1px += q1.y; z1gy += q1.z; z1py += q1.w;
                }
                const float inv = 1.f / 125.f;
                float d0gx = cG0.x - z0gx * inv, d0gy = cG0.y - z0gy * inv;
                float d0px = cP0.x - z0px * inv, d0py = cP0.y - z0py * inv;
                float d1gx = cG1.x - z1gx * inv, d1gy = cG1.y - z1gy * inv;
                float d1px = cP1.x - z1px * inv, d1py = cP1.y - z1py * inv;
                agp += d0gx * d0px + d0gy * d0py + d1gx * d1px + d1gy * d1py;
                agg += d0gx * d0gx + d0gy * d0gy + d1gx * d1gx + d1gy * d1gy;
                app += d0px * d0px + d0py * d0py + d1px * d1px + d1py * d1py;
            }

            // slide: centers = current rows; current = prefetched
            cG0 = vG0; cG1 = vG1; cP0 = vP0; cP1 = vP1;
            vG0 = nG0; vG1 = nG1; vP0 = nP0; vP1 = nP1;
            hG0 = nhG0; hG1 = nhG1; hP0 = nhP0; hP1 = nhP1;
            bufsel ^= 1;
        }

        __syncthreads();
        double v;
        v = bred((double)agp, sh);
        if (tid == 0) atomicAdd(&g_acc[1 + 3 * pair], v);
        __syncthreads();
        v = bred((double)agg, sh);
        if (tid == 0) atomicAdd(&g_acc[2 + 3 * pair], v);
        __syncthreads();
        v = bred((double)app, sh);
        if (tid == 0) atomicAdd(&g_acc[3 + 3 * pair], v);
    } else {
        int rsub = (r3 == 0) ? (bid / 3) : (256 + bid / 3);   // 0..511
        if (rsub < NFRED) {
            // ===== F reduction: sum (F0-F0g)^2 (split accumulator chains) =====
            const float4* __restrict__ A = (const float4*)F0;
            const float4* __restrict__ B = (const float4*)F0g;
            const int n4 = NF / 4;
            float acc0 = 0.f, acc1 = 0.f;
            for (int i = rsub * NT + tid; i < n4; i += NFRED * NT) {
                float4 a = __ldcs(A + i), bb = __ldcs(B + i);
                float d0 = a.x - bb.x, d1 = a.y - bb.y, d2 = a.z - bb.z, d3 = a.w - bb.w;
                acc0 += d0 * d0 + d1 * d1;
                acc1 += d2 * d2 + d3 * d3;
            }
            double v = bred((double)acc0 + (double)acc1, sh);
            if (tid == 0) atomicAdd(&g_acc[0], v);
        } else {
            // ===== Tversky reductions (split accumulator chains) =====
            int rb = rsub - NFRED;
            int pair = rb >= NSRED;
            if (pair) rb -= NSRED;
            const float4* __restrict__ A = (const float4*)(pair ? S1  : S0);
            const float4* __restrict__ B = (const float4*)(pair ? S1g : S0g);
            const int n4 = NI / 4;
            float accp0 = 0.f, accp1 = 0.f, accs0 = 0.f, accs1 = 0.f;
            for (int i = rb * NT + tid; i < n4; i += NSRED * NT) {
                float4 a = __ldcs(A + i), bb = __ldcs(B + i);
                accp0 += a.x * bb.x + a.y * bb.y;
                accp1 += a.z * bb.z + a.w * bb.w;
                accs0 += (a.x + bb.x) + (a.y + bb.y);
                accs1 += (a.z + bb.z) + (a.w + bb.w);
            }
            double v = bred((double)accp0 + (double)accp1, sh);
            if (tid == 0) atomicAdd(&g_acc[7 + 2 * pair], v);
            __syncthreads();
            v = bred((double)accs0 + (double)accs1, sh);
            if (tid == 0) atomicAdd(&g_acc[8 + 2 * pair], v);
        }
    }

    // ===== last-block finalize =====
    if (tid == 0) {
        __threadfence();
        unsigned int old = atomicAdd(&g_count, 1u);
        s_last = (old == NBLK - 1) ? 1u : 0u;
    }
    __syncthreads();
    if (s_last && tid == 0) {
        __threadfence();
        const double LAMBDA = 10.0, BETA = 10.0;
        volatile double* acc = g_acc;

        double reg = sqrt(acc[0]) / (double)NF;

        double lcc_sum = 0.0;
        #pragma unroll
        for (int p = 0; p < 2; p++) {
            double s_gp = acc[1 + 3 * p];
            double s_gg = acc[2 + 3 * p];
            double s_pp = acc[3 + 3 * p];
            double den = s_gg * s_pp;
            den = den > 1e-5 ? den : 1e-5;
            lcc_sum += -(s_gp * s_gp / den) / (double)NI;
        }

        double tv_sum = 0.0;
        #pragma unroll
        for (int p = 0; p < 2; p++) {
            double prod = acc[7 + 2 * p];
            double ssum = acc[8 + 2 * p];
            ssum = ssum > 1e-5 ? ssum : 1e-5;
            tv_sum += -prod / ssum;
        }

        out[0] = (float)(reg + LAMBDA * lcc_sum + BETA * tv_sum);

        // reset state for next graph replay
        #pragma unroll
        for (int i = 0; i < 12; i++) g_acc[i] = 0.0;
        __threadfence();
        g_count = 0u;
    }
}

extern "C" void kernel_launch(void* const* d_in, const int* in_sizes, int n_in,
                              void* d_out, int out_size) {
    const float* F0  = (const float*)d_in[0];
    const float* F0g = (const float*)d_in[1];
    const float* I0  = (const float*)d_in[2];
    const float* I0R = (const float*)d_in[3];
    const float* I1  = (const float*)d_in[4];
    const float* I1R = (const float*)d_in[5];
    const float* S0  = (const float*)d_in[6];
    const float* S0g = (const float*)d_in[7];
    const float* S1  = (const float*)d_in[8];
    const float* S1g = (const float*)d_in[9];
    float* out = (float*)d_out;

    main_kernel<<<NBLK, NT>>>(F0, F0g, I0, I0R, I1, I1R, S0, S0g, S1, S1g, out);
}

// round 15
// speedup vs baseline: 1.5993x; 1.5993x over previous
#include <cuda_runtime.h>
#include <stdint.h>
#include <math.h>

// Shapes: F: (2,3,128,128,128) = 12,582,912 ; I/S: (2,1,128,128,128) = 4,194,304
#define DIM   128
#define DIM2  (128*128)
#define VOL   (128*128*128)
#define NF    12582912
#define NI    4194304

#define NT    384          // 12 warps

// LCC: 2 x-tiles(64) * 16 z-chunks(8) * 2 y-halves(64) * 2 batch * 2 pair = 256
#define NLCC  256
#define NFRED 320
#define NSRED 96
#define NBLK  768          // role = bid % 3 ; r3==1 -> LCC

__device__ double g_acc[12];
__device__ unsigned int g_count;

__device__ __forceinline__ double bred(double v, double* sh) {
    #pragma unroll
    for (int o = 16; o > 0; o >>= 1) v += __shfl_down_sync(0xffffffffu, v, o);
    int lane = threadIdx.x & 31, wid = threadIdx.x >> 5;
    if (lane == 0) sh[wid] = v;
    __syncthreads();
    if (wid == 0) {
        v = (lane < (NT >> 5)) ? sh[lane] : 0.0;
        #pragma unroll
        for (int o = 8; o > 0; o >>= 1) v += __shfl_down_sync(0xffffffffu, v, o);
    }
    return v;  // valid on thread 0
}

// 5-tap x-window sums for the 2 outputs this lane owns (x = 2*tx, 2*tx+1).
__device__ __forceinline__ float2 xsum5(float2 v, float2 h, int tx) {
    float lmx = __shfl_up_sync(0xffffffffu, v.x, 1);
    float lmy = __shfl_up_sync(0xffffffffu, v.y, 1);
    float rpx = __shfl_down_sync(0xffffffffu, v.x, 1);
    float rpy = __shfl_down_sync(0xffffffffu, v.y, 1);
    if (tx == 0)  { lmx = h.x; lmy = h.y; }
    if (tx == 31) { rpx = h.x; rpy = h.y; }
    float m = lmy + v.x + v.y + rpx;
    return make_float2(lmx + m, m + rpy);
}

__global__ __launch_bounds__(NT, 2) void main_kernel(
    const float* __restrict__ F0,  const float* __restrict__ F0g,
    const float* __restrict__ I0,  const float* __restrict__ I0R,
    const float* __restrict__ I1,  const float* __restrict__ I1R,
    const float* __restrict__ S0,  const float* __restrict__ S0g,
    const float* __restrict__ S1,  const float* __restrict__ S1g,
    float* __restrict__ out)
{
    __shared__ __align__(16) float ybuf[2][2][12][128];   // [buf][row][plane][G,P interleaved] = 24 KB
    __shared__ double sh[12];
    __shared__ unsigned int s_last;

    const int bid = blockIdx.x;
    const int tid = threadIdx.x;
    const int r3  = bid % 3;

    if (r3 == 1) {
        // ===== LCC: 2 rows per iteration / x-in-lanes / z-across-warps =====
        int sub = bid / 3;
        int xt = sub & 1;  sub >>= 1;
        int zc = sub & 15; sub >>= 4;
        int yh = sub & 1;  sub >>= 1;
        int b  = sub & 1;  sub >>= 1;
        int pair = sub;

        const float* __restrict__ G = pair ? I1  : I0;
        const float* __restrict__ P = pair ? I1R : I0R;

        const int x0 = xt * 64, z0 = zc * 8, y0 = yh * 64;
        const int tx = tid & 31, w = tid >> 5;      // warp w owns plane z0-2+w
        const int z  = z0 - 2 + w;
        const bool zok = (unsigned)z < DIM;

        const size_t pbase = (size_t)b * VOL + (size_t)(zok ? z : 0) * DIM2
                             + (size_t)x0 + 2 * tx;
        const float* __restrict__ gp = G + pbase;
        const float* __restrict__ pp = P + pbase;

        const bool isL = (tx == 0), isR = (tx == 31);
        const bool haloAct = (isL && x0 > 0) || (isR && x0 + 64 < DIM);
        const int  hoff = isL ? -2 : 2;             // halo offset for lanes 0/31

        const float2 zz = make_float2(0.f, 0.f);

        // current rows 2i, 2i+1 (start: rows 0,1 = y0-2, y0-1)
        float2 vG0 = zz, vG1 = zz, vP0 = zz, vP1 = zz;
        float2 hG0 = zz, hG1 = zz, hP0 = zz, hP1 = zz;
        if (zok) {
            int gy0 = y0 - 2, gy1 = y0 - 1;
            if ((unsigned)gy0 < DIM) {
                size_t ro = (size_t)gy0 * DIM;
                vG0 = *(const float2*)(gp + ro);
                vP0 = *(const float2*)(pp + ro);
                if (haloAct) { hG0 = *(const float2*)(gp + ro + hoff);
                               hP0 = *(const float2*)(pp + ro + hoff); }
            }
            if ((unsigned)gy1 < DIM) {
                size_t ro = (size_t)gy1 * DIM;
                vG1 = *(const float2*)(gp + ro);
                vP1 = *(const float2*)(pp + ro);
                if (haloAct) { hG1 = *(const float2*)(gp + ro + hoff);
                               hP1 = *(const float2*)(pp + ro + hoff); }
            }
        }

        float2 rG[6] = {zz, zz, zz, zz, zz, zz};    // x-sum ring (rows 2i-4 .. 2i+1)
        float2 rP[6] = {zz, zz, zz, zz, zz, zz};
        float2 cG0 = zz, cG1 = zz, cP0 = zz, cP1 = zz;   // centers (rows 2i-2, 2i-1)
        float agp = 0.f, agg = 0.f, app = 0.f;
        const bool mainw = (w >= 2) && (w <= 9);
        int bufsel = 0;

        for (int i = 0; i < 34; i++) {
            // prefetch rows 2i+2, 2i+3 into registers
            float2 nG0 = zz, nG1 = zz, nP0 = zz, nP1 = zz;
            float2 nhG0 = zz, nhG1 = zz, nhP0 = zz, nhP1 = zz;
            if (i < 33 && zok) {
                int gy0 = y0 + 2 * i;          // y of row 2i+2
                int gy1 = gy0 + 1;
                if ((unsigned)gy0 < DIM) {
                    size_t ro = (size_t)gy0 * DIM;
                    nG0 = *(const float2*)(gp + ro);
                    nP0 = *(const float2*)(pp + ro);
                    if (haloAct) { nhG0 = *(const float2*)(gp + ro + hoff);
                                   nhP0 = *(const float2*)(pp + ro + hoff); }
                }
                if ((unsigned)gy1 < DIM) {
                    size_t ro = (size_t)gy1 * DIM;
                    nG1 = *(const float2*)(gp + ro);
                    nP1 = *(const float2*)(pp + ro);
                    if (haloAct) { nhG1 = *(const float2*)(gp + ro + hoff);
                                   nhP1 = *(const float2*)(pp + ro + hoff); }
                }
            }

            // x 5-tap for both rows
            float2 x0G = xsum5(vG0, hG0, tx);
            float2 x1G = xsum5(vG1, hG1, tx);
            float2 x0P = xsum5(vP0, hP0, tx);
            float2 x1P = xsum5(vP1, hP1, tx);

            // ring shift by 2, insert
            rG[0] = rG[2]; rG[1] = rG[3]; rG[2] = rG[4]; rG[3] = rG[5];
            rG[4] = x0G;   rG[5] = x1G;
            rP[0] = rP[2]; rP[1] = rP[3]; rP[2] = rP[4]; rP[3] = rP[5];
            rP[4] = x0P;   rP[5] = x1P;

            // y 5-tap: shared partial m = r1+r2+r3+r4
            float mGx = rG[1].x + rG[2].x + rG[3].x + rG[4].x;
            float mGy = rG[1].y + rG[2].y + rG[3].y + rG[4].y;
            float mPx = rP[1].x + rP[2].x + rP[3].x + rP[4].x;
            float mPy = rP[1].y + rP[2].y + rP[3].y + rP[4].y;
            float y0Gx = rG[0].x + mGx, y0Gy = rG[0].y + mGy;
            float y1Gx = mGx + rG[5].x, y1Gy = mGy + rG[5].y;
            float y0Px = rP[0].x + mPx, y0Py = rP[0].y + mPy;
            float y1Px = mPx + rP[5].x, y1Py = mPy + rP[5].y;

            // publish xy-sums: 2 dense STS.128
            *(float4*)&ybuf[bufsel][0][w][4 * tx] = make_float4(y0Gx, y0Px, y0Gy, y0Py);
            *(float4*)&ybuf[bufsel][1][w][4 * tx] = make_float4(y1Gx, y1Px, y1Gy, y1Py);
            __syncthreads();   // single barrier per 2 rows

            // z 5-tap + accumulate for output rows 2i-2, 2i-1
            if (mainw && i >= 2) {
                float z0gx = 0.f, z0gy = 0.f, z0px = 0.f, z0py = 0.f;
                float z1gx = 0.f, z1gy = 0.f, z1px = 0.f, z1py = 0.f;
                #pragma unroll
                for (int d = 0; d < 5; d++) {
                    float4 q0 = *(const float4*)&ybuf[bufsel][0][w - 2 + d][4 * tx];
                    float4 q1 = *(const float4*)&ybuf[bufsel][1][w - 2 + d][4 * tx];
                    z0gx += q0.x; z0px += q0.y; z0gy += q0.z; z0py += q0.w;
                    z1gx += q1.x; z1px += q1.y; z1gy += q1.z; z1py += q1.w;
                }
                const float inv = 1.f / 125.f;
                float d0gx = cG0.x - z0gx * inv, d0gy = cG0.y - z0gy * inv;
                float d0px = cP0.x - z0px * inv, d0py = cP0.y - z0py * inv;
                float d1gx = cG1.x - z1gx * inv, d1gy = cG1.y - z1gy * inv;
                float d1px = cP1.x - z1px * inv, d1py = cP1.y - z1py * inv;
                agp += d0gx * d0px + d0gy * d0py + d1gx * d1px + d1gy * d1py;
                agg += d0gx * d0gx + d0gy * d0gy + d1gx * d1gx + d1gy * d1gy;
                app += d0px * d0px + d0py * d0py + d1px * d1px + d1py * d1py;
            }

            // slide: centers = current rows; current = prefetched
            cG0 = vG0; cG1 = vG1; cP0 = vP0; cP1 = vP1;
            vG0 = nG0; vG1 = nG1; vP0 = nP0; vP1 = nP1;
            hG0 = nhG0; hG1 = nhG1; hP0 = nhP0; hP1 = nhP1;
            bufsel ^= 1;
        }

        __syncthreads();
        double v;
        v = bred((double)agp, sh);
        if (tid == 0) atomicAdd(&g_acc[1 + 3 * pair], v);
        __syncthreads();
        v = bred((double)agg, sh);
        if (tid == 0) atomicAdd(&g_acc[2 + 3 * pair], v);
        __syncthreads();
        v = bred((double)app, sh);
        if (tid == 0) atomicAdd(&g_acc[3 + 3 * pair], v);
    } else {
        int rsub = (r3 == 0) ? (bid / 3) : (256 + bid / 3);   // 0..511
        if (rsub < NFRED) {
            // ===== F reduction: sum (F0-F0g)^2 (split accumulator chains) =====
            const float4* __restrict__ A = (const float4*)F0;
            const float4* __restrict__ B = (const float4*)F0g;
            const int n4 = NF / 4;
            float acc0 = 0.f, acc1 = 0.f;
            for (int i = rsub * NT + tid; i < n4; i += NFRED * NT) {
                float4 a = __ldcs(A + i), bb = __ldcs(B + i);
                float d0 = a.x - bb.x, d1 = a.y - bb.y, d2 = a.z - bb.z, d3 = a.w - bb.w;
                acc0 += d0 * d0 + d1 * d1;
                acc1 += d2 * d2 + d3 * d3;
            }
            double v = bred((double)acc0 + (double)acc1, sh);
            if (tid == 0) atomicAdd(&g_acc[0], v);
        } else {
            // ===== Tversky reductions (split accumulator chains) =====
            int rb = rsub - NFRED;
            int pair = rb >= NSRED;
            if (pair) rb -= NSRED;
            const float4* __restrict__ A = (const float4*)(pair ? S1  : S0);
            const float4* __restrict__ B = (const float4*)(pair ? S1g : S0g);
            const int n4 = NI / 4;
            float accp0 = 0.f, accp1 = 0.f, accs0 = 0.f, accs1 = 0.f;
            for (int i = rb * NT + tid; i < n4; i += NSRED * NT) {
                float4 a = __ldcs(A + i), bb = __ldcs(B + i);
                accp0 += a.x * bb.x + a.y * bb.y;
                accp1 += a.z * bb.z + a.w * bb.w;
                accs0 += (a.x + bb.x) + (a.y + bb.y);
                accs1 += (a.z + bb.z) + (a.w + bb.w);
            }
            double v = bred((double)accp0 + (double)accp1, sh);
            if (tid == 0) atomicAdd(&g_acc[7 + 2 * pair], v);
            __syncthreads();
            v = bred((double)accs0 + (double)accs1, sh);
            if (tid == 0) atomicAdd(&g_acc[8 + 2 * pair], v);
        }
    }

    // ===== last-block finalize =====
    if (tid == 0) {
        __threadfence();
        unsigned int old = atomicAdd(&g_count, 1u);
        s_last = (old == NBLK - 1) ? 1u : 0u;
    }
    __syncthreads();
    if (s_last && tid == 0) {
        __threadfence();
        const double LAMBDA = 10.0, BETA = 10.0;
        volatile double* acc = g_acc;

        double reg = sqrt(acc[0]) / (double)NF;

        double lcc_sum = 0.0;
        #pragma unroll
        for (int p = 0; p < 2; p++) {
            double s_gp = acc[1 + 3 * p];
            double s_gg = acc[2 + 3 * p];
            double s_pp = acc[3 + 3 * p];
            double den = s_gg * s_pp;
            den = den > 1e-5 ? den : 1e-5;
            lcc_sum += -(s_gp * s_gp / den) / (double)NI;
        }

        double tv_sum = 0.0;
        #pragma unroll
        for (int p = 0; p < 2; p++) {
            double prod = acc[7 + 2 * p];
            double ssum = acc[8 + 2 * p];
            ssum = ssum > 1e-5 ? ssum : 1e-5;
            tv_sum += -prod / ssum;
        }

        out[0] = (float)(reg + LAMBDA * lcc_sum + BETA * tv_sum);

        // reset state for next graph replay
        #pragma unroll
        for (int i = 0; i < 12; i++) g_acc[i] = 0.0;
        __threadfence();
        g_count = 0u;
    }
}

extern "C" void kernel_launch(void* const* d_in, const int* in_sizes, int n_in,
                              void* d_out, int out_size) {
    const float* F0  = (const float*)d_in[0];
    const float* F0g = (const float*)d_in[1];
    const float* I0  = (const float*)d_in[2];
    const float* I0R = (const float*)d_in[3];
    const float* I1  = (const float*)d_in[4];
    const float* I1R = (const float*)d_in[5];
    const float* S0  = (const float*)d_in[6];
    const float* S0g = (const float*)d_in[7];
    const float* S1  = (const float*)d_in[8];
    const float* S1g = (const float*)d_in[9];
    float* out = (float*)d_out;

    main_kernel<<<NBLK, NT>>>(F0, F0g, I0, I0R, I1, I1R, S0, S0g, S1, S1g, out);
}